// round 13
// baseline (speedup 1.0000x reference)
#include <cuda_runtime.h>
#include <cuda_bf16.h>
#include <cstdint>

// out[b,c] = H @ x[b,c] @ H^T for 65536 independent 32x32 fp32 matrices.
// mma.sync bf16 path (plain sm_103 target). bf16 hi/lo split, 3 cross terms,
// fp32 accumulation -> rel err ~5e-6. One warp = one matrix, fully
// register-resident: X frags straight from gmem, movmatrix in-register
// transpose, H frags shared by both stages.
// R12 (latency round): launch_bounds(128,6) for 24 warps/SM; X LDGs issued
// before H staging (raw float2 in regs); per-mi accumulator lifetimes so the
// whole kernel fits the 85-reg budget without spills.

#define NTHREADS 128
#define HSTR 40                  // H smem row pitch in bf16 (32 + 8 pad)

__device__ __forceinline__ uint32_t lds32(const unsigned short* p) {
    return *reinterpret_cast<const uint32_t*>(p);
}

__device__ __forceinline__ uint32_t pack_bf16x2(float hi, float lo) {
    uint32_t r;
    asm("cvt.rn.bf16x2.f32 %0, %1, %2;" : "=r"(r) : "f"(hi), "f"(lo));
    return r;
}
__device__ __forceinline__ float bf16lo_f(uint32_t p) {
    return __bfloat162float(__ushort_as_bfloat16((unsigned short)(p & 0xFFFFu)));
}
__device__ __forceinline__ float bf16hi_f(uint32_t p) {
    return __bfloat162float(__ushort_as_bfloat16((unsigned short)(p >> 16)));
}
// split two f32 (v0=k, v1=k+1) into packed bf16x2 hi + residual lo
__device__ __forceinline__ void split2(float v0, float v1,
                                       uint32_t& h, uint32_t& l) {
    h = pack_bf16x2(v1, v0);
    l = pack_bf16x2(v1 - bf16hi_f(h), v0 - bf16lo_f(h));
}

__device__ __forceinline__ uint32_t movm_t(uint32_t a) {
    uint32_t d;
    asm volatile("movmatrix.sync.aligned.m8n8.trans.b16 %0, %1;"
                 : "=r"(d) : "r"(a));
    return d;
}

__device__ __forceinline__ void mma16816(float* d, const uint32_t* a,
                                         uint32_t b0, uint32_t b1) {
    asm volatile(
        "mma.sync.aligned.m16n8k16.row.col.f32.bf16.bf16.f32 "
        "{%0,%1,%2,%3}, {%4,%5,%6,%7}, {%8,%9}, {%0,%1,%2,%3};"
        : "+f"(d[0]), "+f"(d[1]), "+f"(d[2]), "+f"(d[3])
        : "r"(a[0]), "r"(a[1]), "r"(a[2]), "r"(a[3]), "r"(b0), "r"(b1));
}

__global__ __launch_bounds__(NTHREADS, 6)
void dct2d_mma_kernel(const float* __restrict__ x,
                      const float* __restrict__ H,
                      float* __restrict__ out,
                      int nMat)
{
    __shared__ __align__(16) unsigned short Hh[32 * HSTR];
    __shared__ __align__(16) unsigned short Hl[32 * HSTR];

    const int tid  = threadIdx.x;
    const int w    = tid >> 5;
    const int lane = tid & 31;
    const int g    = lane >> 2;   // mma groupID 0..7
    const int t    = lane & 3;    // thread-in-group 0..3

    // ---- issue all X loads FIRST (DRAM latency starts now) ----
    const float* __restrict__ Xw = x + ((size_t)blockIdx.x * 4 + w) * 1024;
    float2 xv[2][2][4];
    #pragma unroll
    for (int mi = 0; mi < 2; mi++)
        #pragma unroll
        for (int ki = 0; ki < 2; ki++) {
            int r0 = 16 * mi + g;
            int c0 = 16 * ki + 2 * t;
            xv[mi][ki][0] = *reinterpret_cast<const float2*>(Xw + r0 * 32 + c0);
            xv[mi][ki][1] = *reinterpret_cast<const float2*>(Xw + (r0 + 8) * 32 + c0);
            xv[mi][ki][2] = *reinterpret_cast<const float2*>(Xw + r0 * 32 + c0 + 8);
            xv[mi][ki][3] = *reinterpret_cast<const float2*>(Xw + (r0 + 8) * 32 + c0 + 8);
        }

    // ---- stage H into smem (hi/lo split), overlapped with X in flight ----
    #pragma unroll
    for (int e = tid; e < 1024; e += NTHREADS) {
        int r = e >> 5, c = e & 31;
        float v = H[e];
        __nv_bfloat16 hb = __float2bfloat16_rn(v);
        Hh[r * HSTR + c] = __bfloat16_as_ushort(hb);
        Hl[r * HSTR + c] =
            __bfloat16_as_ushort(__float2bfloat16_rn(v - __bfloat162float(hb)));
    }
    __syncthreads();

    // ---- H fragments, loaded once, reused by both stages ----
    uint32_t Hf[4][2][2], Hfl[4][2][2];
    #pragma unroll
    for (int r = 0; r < 4; r++)
        #pragma unroll
        for (int ki = 0; ki < 2; ki++) {
            int off = (8 * r + g) * HSTR + 16 * ki + 2 * t;
            Hf[r][ki][0]  = lds32(Hh + off);
            Hf[r][ki][1]  = lds32(Hh + off + 8);
            Hfl[r][ki][0] = lds32(Hl + off);
            Hfl[r][ki][1] = lds32(Hl + off + 8);
        }

    // ---- convert X to bf16 hi/lo packed frags (raw regs die here) ----
    uint32_t Ah[2][2][4], Al[2][2][4];
    #pragma unroll
    for (int mi = 0; mi < 2; mi++)
        #pragma unroll
        for (int ki = 0; ki < 2; ki++)
            #pragma unroll
            for (int r = 0; r < 4; r++)
                split2(xv[mi][ki][r].x, xv[mi][ki][r].y,
                       Ah[mi][ki][r], Al[mi][ki][r]);

    // ================= stage 1 (per mi) + handoff =================
    uint32_t B2h[4][2][2], B2l[4][2][2];
    #pragma unroll
    for (int mi = 0; mi < 2; mi++) {
        float acc[4][4];
        #pragma unroll
        for (int ni = 0; ni < 4; ni++)
            #pragma unroll
            for (int r = 0; r < 4; r++) acc[ni][r] = 0.0f;

        #pragma unroll
        for (int ni = 0; ni < 4; ni++)
            #pragma unroll
            for (int ki = 0; ki < 2; ki++) {
                mma16816(acc[ni], Ah[mi][ki], Hf[ni][ki][0],  Hf[ni][ki][1]);
                mma16816(acc[ni], Ah[mi][ki], Hfl[ni][ki][0], Hfl[ni][ki][1]);
                mma16816(acc[ni], Al[mi][ki], Hf[ni][ki][0],  Hf[ni][ki][1]);
            }

        // in-register transpose via movmatrix -> stage-2 B frags
        #pragma unroll
        for (int ni = 0; ni < 4; ni++) {
            uint32_t h01, l01, h23, l23;
            split2(acc[ni][0], acc[ni][1], h01, l01);
            split2(acc[ni][2], acc[ni][3], h23, l23);
            B2h[ni][mi][0] = movm_t(h01);
            B2h[ni][mi][1] = movm_t(h23);
            B2l[ni][mi][0] = movm_t(l01);
            B2l[ni][mi][1] = movm_t(l23);
        }
    }

    // ================= stage 2 (per mi) + store =================
    float* __restrict__ dst = out + ((size_t)blockIdx.x * 4 + w) * 1024;
    #pragma unroll
    for (int mi = 0; mi < 2; mi++) {
        float acc2[4][4];
        #pragma unroll
        for (int ni = 0; ni < 4; ni++)
            #pragma unroll
            for (int r = 0; r < 4; r++) acc2[ni][r] = 0.0f;

        #pragma unroll
        for (int ni = 0; ni < 4; ni++)
            #pragma unroll
            for (int ki = 0; ki < 2; ki++) {
                uint32_t a2h[4] = {Hf[2 * mi][ki][0],  Hf[2 * mi + 1][ki][0],
                                   Hf[2 * mi][ki][1],  Hf[2 * mi + 1][ki][1]};
                uint32_t a2l[4] = {Hfl[2 * mi][ki][0], Hfl[2 * mi + 1][ki][0],
                                   Hfl[2 * mi][ki][1], Hfl[2 * mi + 1][ki][1]};
                mma16816(acc2[ni], a2h, B2h[ni][ki][0], B2h[ni][ki][1]);
                mma16816(acc2[ni], a2h, B2l[ni][ki][0], B2l[ni][ki][1]);
                mma16816(acc2[ni], a2l, B2h[ni][ki][0], B2h[ni][ki][1]);
            }

        #pragma unroll
        for (int ni = 0; ni < 4; ni++) {
            int l0 = 16 * mi + g;
            int n0 = 8 * ni + 2 * t;
            *reinterpret_cast<float2*>(&dst[l0 * 32 + n0]) =
                make_float2(acc2[ni][0], acc2[ni][1]);
            *reinterpret_cast<float2*>(&dst[(l0 + 8) * 32 + n0]) =
                make_float2(acc2[ni][2], acc2[ni][3]);
        }
    }
}

extern "C" void kernel_launch(void* const* d_in, const int* in_sizes, int n_in,
                              void* d_out, int out_size)
{
    const float* x = (const float*)d_in[0];   // [B, C, 32, 32] fp32
    const float* H = (const float*)d_in[1];   // [32, 32] fp32
    float* out = (float*)d_out;

    int nMat = in_sizes[0] / 1024;            // 65536 (divisible by 4)
    int blocks = nMat / 4;

    dct2d_mma_kernel<<<blocks, NTHREADS>>>(x, H, out, nMat);
}

// round 14
// speedup vs baseline: 1.1379x; 1.1379x over previous
#include <cuda_runtime.h>
#include <cuda_bf16.h>
#include <cstdint>

// out[b,c] = H @ x[b,c] @ H^T for 65536 independent 32x32 fp32 matrices.
// mma.sync bf16 path (plain sm_103 target). bf16 hi/lo split, 3 cross terms,
// fp32 accumulation -> rel err ~5e-6. One warp = one matrix, fully
// register-resident: X frags straight from gmem, movmatrix in-register
// transpose, H frags shared by both stages.
// R13 = R11 schedule (8 parallel acc chains, occ-4 / ~112 regs: R12 proved
// per-warp ILP beats occupancy here) + front-loaded X LDGs (overlap DRAM
// latency with H staging) + split-term MMAs interleaved across mi so
// dependent HMMA chains get a 2-instruction gap.

#define NTHREADS 128
#define HSTR 40                  // H smem row pitch in bf16 (32 + 8 pad)

__device__ __forceinline__ uint32_t lds32(const unsigned short* p) {
    return *reinterpret_cast<const uint32_t*>(p);
}

__device__ __forceinline__ uint32_t pack_bf16x2(float hi, float lo) {
    uint32_t r;
    asm("cvt.rn.bf16x2.f32 %0, %1, %2;" : "=r"(r) : "f"(hi), "f"(lo));
    return r;
}
__device__ __forceinline__ float bf16lo_f(uint32_t p) {
    return __uint_as_float(p << 16);
}
__device__ __forceinline__ float bf16hi_f(uint32_t p) {
    return __uint_as_float(p & 0xFFFF0000u);
}
// split two f32 (v0=k, v1=k+1) into packed bf16x2 hi + residual lo
__device__ __forceinline__ void split2(float v0, float v1,
                                       uint32_t& h, uint32_t& l) {
    h = pack_bf16x2(v1, v0);
    l = pack_bf16x2(v1 - bf16hi_f(h), v0 - bf16lo_f(h));
}

__device__ __forceinline__ uint32_t movm_t(uint32_t a) {
    uint32_t d;
    asm volatile("movmatrix.sync.aligned.m8n8.trans.b16 %0, %1;"
                 : "=r"(d) : "r"(a));
    return d;
}

__device__ __forceinline__ void mma16816(float* d, const uint32_t* a,
                                         uint32_t b0, uint32_t b1) {
    asm("mma.sync.aligned.m16n8k16.row.col.f32.bf16.bf16.f32 "
        "{%0,%1,%2,%3}, {%4,%5,%6,%7}, {%8,%9}, {%0,%1,%2,%3};"
        : "+f"(d[0]), "+f"(d[1]), "+f"(d[2]), "+f"(d[3])
        : "r"(a[0]), "r"(a[1]), "r"(a[2]), "r"(a[3]), "r"(b0), "r"(b1));
}

__global__ __launch_bounds__(NTHREADS, 4)
void dct2d_mma_kernel(const float* __restrict__ x,
                      const float* __restrict__ H,
                      float* __restrict__ out,
                      int nMat)
{
    __shared__ __align__(16) unsigned short Hh[32 * HSTR];
    __shared__ __align__(16) unsigned short Hl[32 * HSTR];

    const int tid  = threadIdx.x;
    const int w    = tid >> 5;
    const int lane = tid & 31;
    const int g    = lane >> 2;   // mma groupID 0..7
    const int t    = lane & 3;    // thread-in-group 0..3

    // ---- issue all X loads FIRST (DRAM latency starts now) ----
    const float* __restrict__ Xw = x + ((size_t)blockIdx.x * 4 + w) * 1024;
    float2 xv[2][2][4];
    #pragma unroll
    for (int mi = 0; mi < 2; mi++)
        #pragma unroll
        for (int ki = 0; ki < 2; ki++) {
            int r0 = 16 * mi + g;
            int c0 = 16 * ki + 2 * t;
            xv[mi][ki][0] = *reinterpret_cast<const float2*>(Xw + r0 * 32 + c0);
            xv[mi][ki][1] = *reinterpret_cast<const float2*>(Xw + (r0 + 8) * 32 + c0);
            xv[mi][ki][2] = *reinterpret_cast<const float2*>(Xw + r0 * 32 + c0 + 8);
            xv[mi][ki][3] = *reinterpret_cast<const float2*>(Xw + (r0 + 8) * 32 + c0 + 8);
        }

    // ---- stage H into smem (hi/lo split), overlapped with X in flight ----
    #pragma unroll
    for (int e = tid; e < 1024; e += NTHREADS) {
        int r = e >> 5, c = e & 31;
        float v = H[e];
        __nv_bfloat16 hb = __float2bfloat16_rn(v);
        Hh[r * HSTR + c] = __bfloat16_as_ushort(hb);
        Hl[r * HSTR + c] =
            __bfloat16_as_ushort(__float2bfloat16_rn(v - __bfloat162float(hb)));
    }
    __syncthreads();

    // ---- H fragments, loaded once, reused by both stages ----
    uint32_t Hf[4][2][2], Hfl[4][2][2];
    #pragma unroll
    for (int r = 0; r < 4; r++)
        #pragma unroll
        for (int ki = 0; ki < 2; ki++) {
            int off = (8 * r + g) * HSTR + 16 * ki + 2 * t;
            Hf[r][ki][0]  = lds32(Hh + off);
            Hf[r][ki][1]  = lds32(Hh + off + 8);
            Hfl[r][ki][0] = lds32(Hl + off);
            Hfl[r][ki][1] = lds32(Hl + off + 8);
        }

    // ---- convert X to bf16 hi/lo packed frags ----
    uint32_t Ah[2][2][4], Al[2][2][4];
    #pragma unroll
    for (int mi = 0; mi < 2; mi++)
        #pragma unroll
        for (int ki = 0; ki < 2; ki++)
            #pragma unroll
            for (int r = 0; r < 4; r++)
                split2(xv[mi][ki][r].x, xv[mi][ki][r].y,
                       Ah[mi][ki][r], Al[mi][ki][r]);

    // ================= stage 1: U = X @ H^T =================
    float acc[2][4][4];
    #pragma unroll
    for (int mi = 0; mi < 2; mi++)
        #pragma unroll
        for (int ni = 0; ni < 4; ni++)
            #pragma unroll
            for (int r = 0; r < 4; r++) acc[mi][ni][r] = 0.0f;

    // term-outer / mi-inner: consecutive MMAs hit different accumulators
    #pragma unroll
    for (int ni = 0; ni < 4; ni++)
        #pragma unroll
        for (int ki = 0; ki < 2; ki++) {
            uint32_t bh0 = Hf[ni][ki][0],  bh1 = Hf[ni][ki][1];
            uint32_t bl0 = Hfl[ni][ki][0], bl1 = Hfl[ni][ki][1];
            #pragma unroll
            for (int mi = 0; mi < 2; mi++) mma16816(acc[mi][ni], Ah[mi][ki], bh0, bh1);
            #pragma unroll
            for (int mi = 0; mi < 2; mi++) mma16816(acc[mi][ni], Ah[mi][ki], bl0, bl1);
            #pragma unroll
            for (int mi = 0; mi < 2; mi++) mma16816(acc[mi][ni], Al[mi][ki], bh0, bh1);
        }

    // ---- handoff: in-register transpose via movmatrix ----
    uint32_t B2h[4][2][2], B2l[4][2][2];
    #pragma unroll
    for (int mi = 0; mi < 2; mi++)
        #pragma unroll
        for (int ni = 0; ni < 4; ni++) {
            uint32_t h01, l01, h23, l23;
            split2(acc[mi][ni][0], acc[mi][ni][1], h01, l01);
            split2(acc[mi][ni][2], acc[mi][ni][3], h23, l23);
            B2h[ni][mi][0] = movm_t(h01);
            B2h[ni][mi][1] = movm_t(h23);
            B2l[ni][mi][0] = movm_t(l01);
            B2l[ni][mi][1] = movm_t(l23);
        }

    // ================= stage 2: Out = H @ U =================
    float acc2[2][4][4];
    #pragma unroll
    for (int mi = 0; mi < 2; mi++)
        #pragma unroll
        for (int ni = 0; ni < 4; ni++)
            #pragma unroll
            for (int r = 0; r < 4; r++) acc2[mi][ni][r] = 0.0f;

    #pragma unroll
    for (int ni = 0; ni < 4; ni++)
        #pragma unroll
        for (int ki = 0; ki < 2; ki++) {
            uint32_t bh0 = B2h[ni][ki][0], bh1 = B2h[ni][ki][1];
            uint32_t bl0 = B2l[ni][ki][0], bl1 = B2l[ni][ki][1];
            uint32_t a2h[2][4], a2l[2][4];
            #pragma unroll
            for (int mi = 0; mi < 2; mi++) {
                a2h[mi][0] = Hf[2 * mi][ki][0];  a2h[mi][1] = Hf[2 * mi + 1][ki][0];
                a2h[mi][2] = Hf[2 * mi][ki][1];  a2h[mi][3] = Hf[2 * mi + 1][ki][1];
                a2l[mi][0] = Hfl[2 * mi][ki][0]; a2l[mi][1] = Hfl[2 * mi + 1][ki][0];
                a2l[mi][2] = Hfl[2 * mi][ki][1]; a2l[mi][3] = Hfl[2 * mi + 1][ki][1];
            }
            #pragma unroll
            for (int mi = 0; mi < 2; mi++) mma16816(acc2[mi][ni], a2h[mi], bh0, bh1);
            #pragma unroll
            for (int mi = 0; mi < 2; mi++) mma16816(acc2[mi][ni], a2h[mi], bl0, bl1);
            #pragma unroll
            for (int mi = 0; mi < 2; mi++) mma16816(acc2[mi][ni], a2l[mi], bh0, bh1);
        }

    // ---- store: c0/c1 adjacent cols -> coalesced float2 ----
    float* __restrict__ dst = out + ((size_t)blockIdx.x * 4 + w) * 1024;
    #pragma unroll
    for (int mi = 0; mi < 2; mi++)
        #pragma unroll
        for (int ni = 0; ni < 4; ni++) {
            int l0 = 16 * mi + g;
            int n0 = 8 * ni + 2 * t;
            *reinterpret_cast<float2*>(&dst[l0 * 32 + n0]) =
                make_float2(acc2[mi][ni][0], acc2[mi][ni][1]);
            *reinterpret_cast<float2*>(&dst[(l0 + 8) * 32 + n0]) =
                make_float2(acc2[mi][ni][2], acc2[mi][ni][3]);
        }
}

extern "C" void kernel_launch(void* const* d_in, const int* in_sizes, int n_in,
                              void* d_out, int out_size)
{
    const float* x = (const float*)d_in[0];   // [B, C, 32, 32] fp32
    const float* H = (const float*)d_in[1];   // [32, 32] fp32
    float* out = (float*)d_out;

    int nMat = in_sizes[0] / 1024;            // 65536 (divisible by 4)
    int blocks = nMat / 4;

    dct2d_mma_kernel<<<blocks, NTHREADS>>>(x, H, out, nMat);
}

// round 15
// speedup vs baseline: 1.2314x; 1.0822x over previous
#include <cuda_runtime.h>
#include <cuda_bf16.h>
#include <cstdint>

// out[b,c] = H @ x[b,c] @ H^T for 65536 independent 32x32 fp32 matrices.
// mma.sync bf16 path, hi/lo split (3 cross terms), fp32 accumulation.
// R14: DCT even/odd butterfly applied to stage 1 on the TENSOR path:
//   H[j][31-k] = (-1)^j H[j][k]  =>  U[:,even]=E@He^T, U[:,odd]=O@Ho^T with
//   E/O = X[:,k] +/- X[:,31-k], k<16  => stage-1 MMAs 48 -> 24.
// Trick: compute Utilde = [Ue | Uo] (column-relabeled U). Its accumulators
// have exactly the R13 layout, so the movmatrix handoff + stage 2 are
// unchanged; the column permutation is undone in the store epilogue where
// even/odd acc pairs merge into 4 consecutive columns -> 8 STG.128.

#define NTHREADS 128
#define HSTR 40                  // full-H smem pitch in bf16 (32 + 8 pad)
#define EPITCH 24                // He/Ho table pitch in bf16 (conflict-free)

__device__ __forceinline__ uint32_t lds32(const unsigned short* p) {
    return *reinterpret_cast<const uint32_t*>(p);
}

__device__ __forceinline__ uint32_t pack_bf16x2(float hi, float lo) {
    uint32_t r;
    asm("cvt.rn.bf16x2.f32 %0, %1, %2;" : "=r"(r) : "f"(hi), "f"(lo));
    return r;
}
__device__ __forceinline__ float bf16lo_f(uint32_t p) {
    return __uint_as_float(p << 16);
}
__device__ __forceinline__ float bf16hi_f(uint32_t p) {
    return __uint_as_float(p & 0xFFFF0000u);
}
// split two f32 (v0=k, v1=k+1) into packed bf16x2 hi + residual lo
__device__ __forceinline__ void split2(float v0, float v1,
                                       uint32_t& h, uint32_t& l) {
    h = pack_bf16x2(v1, v0);
    l = pack_bf16x2(v1 - bf16hi_f(h), v0 - bf16lo_f(h));
}

__device__ __forceinline__ uint32_t movm_t(uint32_t a) {
    uint32_t d;
    asm volatile("movmatrix.sync.aligned.m8n8.trans.b16 %0, %1;"
                 : "=r"(d) : "r"(a));
    return d;
}

__device__ __forceinline__ void mma16816(float* d, const uint32_t* a,
                                         uint32_t b0, uint32_t b1) {
    asm("mma.sync.aligned.m16n8k16.row.col.f32.bf16.bf16.f32 "
        "{%0,%1,%2,%3}, {%4,%5,%6,%7}, {%8,%9}, {%0,%1,%2,%3};"
        : "+f"(d[0]), "+f"(d[1]), "+f"(d[2]), "+f"(d[3])
        : "r"(a[0]), "r"(a[1]), "r"(a[2]), "r"(a[3]), "r"(b0), "r"(b1));
}

__global__ __launch_bounds__(NTHREADS, 5)
void dct2d_mma_kernel(const float* __restrict__ x,
                      const float* __restrict__ H,
                      float* __restrict__ out,
                      int nMat)
{
    __shared__ __align__(16) unsigned short Hfh[32 * HSTR];
    __shared__ __align__(16) unsigned short Hfl_[32 * HSTR];
    __shared__ __align__(16) unsigned short Heh[16 * EPITCH];
    __shared__ __align__(16) unsigned short Hel[16 * EPITCH];
    __shared__ __align__(16) unsigned short Hoh[16 * EPITCH];
    __shared__ __align__(16) unsigned short Hol[16 * EPITCH];

    const int tid  = threadIdx.x;
    const int w    = tid >> 5;
    const int lane = tid & 31;
    const int g    = lane >> 2;   // mma groupID 0..7
    const int t    = lane & 3;    // thread-in-group 0..3

    // ---- issue all X loads FIRST (rows k and partner rows for butterfly) ----
    const float* __restrict__ Xw = x + ((size_t)blockIdx.x * 4 + w) * 1024;
    float2 v0[2][2], v1[2][2], p0[2][2], p1[2][2];
    #pragma unroll
    for (int mi = 0; mi < 2; mi++)
        #pragma unroll
        for (int rh = 0; rh < 2; rh++) {
            const float* rp = Xw + (16 * mi + 8 * rh + g) * 32;
            v0[mi][rh] = *reinterpret_cast<const float2*>(rp + 2 * t);        // cols 2t,2t+1
            v1[mi][rh] = *reinterpret_cast<const float2*>(rp + 8 + 2 * t);    // cols 8+2t,..
            p0[mi][rh] = *reinterpret_cast<const float2*>(rp + 30 - 2 * t);   // cols 30-2t,31-2t
            p1[mi][rh] = *reinterpret_cast<const float2*>(rp + 22 - 2 * t);   // cols 22-2t,23-2t
        }

    // ---- stage H into smem: full table + even/odd half-K tables ----
    #pragma unroll
    for (int e = tid; e < 1024; e += NTHREADS) {
        int r = e >> 5, c = e & 31;
        float v = H[e];
        __nv_bfloat16 hb = __float2bfloat16_rn(v);
        unsigned short hh = __bfloat16_as_ushort(hb);
        unsigned short hl =
            __bfloat16_as_ushort(__float2bfloat16_rn(v - __bfloat162float(hb)));
        Hfh[r * HSTR + c]  = hh;
        Hfl_[r * HSTR + c] = hl;
        if (c < 16) {
            int hr = r >> 1;
            if (r & 1) { Hoh[hr * EPITCH + c] = hh; Hol[hr * EPITCH + c] = hl; }
            else       { Heh[hr * EPITCH + c] = hh; Hel[hr * EPITCH + c] = hl; }
        }
    }
    __syncthreads();

    // ---- stage-1 B frags from He/Ho (K=16 tables) ----
    uint32_t Beh[2][2], Bel[2][2], Boh[2][2], Bol[2][2];
    #pragma unroll
    for (int ni = 0; ni < 2; ni++) {
        int off = (8 * ni + g) * EPITCH + 2 * t;
        Beh[ni][0] = lds32(Heh + off);  Beh[ni][1] = lds32(Heh + off + 8);
        Bel[ni][0] = lds32(Hel + off);  Bel[ni][1] = lds32(Hel + off + 8);
        Boh[ni][0] = lds32(Hoh + off);  Boh[ni][1] = lds32(Hoh + off + 8);
        Bol[ni][0] = lds32(Hol + off);  Bol[ni][1] = lds32(Hol + off + 8);
    }

    // ---- butterfly E/O in registers + split to stage-1 A frags ----
    // p0 = (X[31-(2t+1)], X[31-2t]) reversed; partner of k=2t is p0.y etc.
    uint32_t Aeh[2][4], Ael[2][4], Aoh[2][4], Aol[2][4];
    #pragma unroll
    for (int mi = 0; mi < 2; mi++)
        #pragma unroll
        for (int rh = 0; rh < 2; rh++) {
            float2 a = v0[mi][rh], b = p0[mi][rh];
            float2 c = v1[mi][rh], d = p1[mi][rh];
            float e0 = a.x + b.y, e1 = a.y + b.x;
            float o0 = a.x - b.y, o1 = a.y - b.x;
            float e2 = c.x + d.y, e3 = c.y + d.x;
            float o2 = c.x - d.y, o3 = c.y - d.x;
            split2(e0, e1, Aeh[mi][rh],     Ael[mi][rh]);       // k=2t pair
            split2(e2, e3, Aeh[mi][2 + rh], Ael[mi][2 + rh]);   // k=8+2t pair
            split2(o0, o1, Aoh[mi][rh],     Aol[mi][rh]);
            split2(o2, o3, Aoh[mi][2 + rh], Aol[mi][2 + rh]);
        }

    // ================= stage 1: Utilde = [E@He^T | O@Ho^T], 24 MMAs ========
    // acc[mi][ni] = Ue cols (ni=0,1); acc[mi][2+ni] = Uo cols.
    float acc[2][4][4];
    #pragma unroll
    for (int mi = 0; mi < 2; mi++)
        #pragma unroll
        for (int ni = 0; ni < 4; ni++)
            #pragma unroll
            for (int r = 0; r < 4; r++) acc[mi][ni][r] = 0.0f;

    #pragma unroll
    for (int ni = 0; ni < 2; ni++) {
        #pragma unroll
        for (int mi = 0; mi < 2; mi++) mma16816(acc[mi][ni],     Aeh[mi], Beh[ni][0], Beh[ni][1]);
        #pragma unroll
        for (int mi = 0; mi < 2; mi++) mma16816(acc[mi][2 + ni], Aoh[mi], Boh[ni][0], Boh[ni][1]);
        #pragma unroll
        for (int mi = 0; mi < 2; mi++) mma16816(acc[mi][ni],     Aeh[mi], Bel[ni][0], Bel[ni][1]);
        #pragma unroll
        for (int mi = 0; mi < 2; mi++) mma16816(acc[mi][2 + ni], Aoh[mi], Bol[ni][0], Bol[ni][1]);
        #pragma unroll
        for (int mi = 0; mi < 2; mi++) mma16816(acc[mi][ni],     Ael[mi], Beh[ni][0], Beh[ni][1]);
        #pragma unroll
        for (int mi = 0; mi < 2; mi++) mma16816(acc[mi][2 + ni], Aol[mi], Boh[ni][0], Boh[ni][1]);
    }

    // ---- full-H fragments for stage 2 (LDS latency overlaps handoff) ----
    uint32_t Hf[4][2][2], Hfl[4][2][2];
    #pragma unroll
    for (int r = 0; r < 4; r++)
        #pragma unroll
        for (int ki = 0; ki < 2; ki++) {
            int off = (8 * r + g) * HSTR + 16 * ki + 2 * t;
            Hf[r][ki][0]  = lds32(Hfh + off);
            Hf[r][ki][1]  = lds32(Hfh + off + 8);
            Hfl[r][ki][0] = lds32(Hfl_ + off);
            Hfl[r][ki][1] = lds32(Hfl_ + off + 8);
        }

    // ---- handoff: in-register transpose (Utilde layout == R13 layout) ----
    uint32_t B2h[4][2][2], B2l[4][2][2];
    #pragma unroll
    for (int mi = 0; mi < 2; mi++)
        #pragma unroll
        for (int ni = 0; ni < 4; ni++) {
            uint32_t h01, l01, h23, l23;
            split2(acc[mi][ni][0], acc[mi][ni][1], h01, l01);
            split2(acc[mi][ni][2], acc[mi][ni][3], h23, l23);
            B2h[ni][mi][0] = movm_t(h01);
            B2h[ni][mi][1] = movm_t(h23);
            B2l[ni][mi][0] = movm_t(l01);
            B2l[ni][mi][1] = movm_t(l23);
        }

    // ================= stage 2: out~ = H @ Utilde (48 MMAs) =================
    float acc2[2][4][4];
    #pragma unroll
    for (int mi = 0; mi < 2; mi++)
        #pragma unroll
        for (int ni = 0; ni < 4; ni++)
            #pragma unroll
            for (int r = 0; r < 4; r++) acc2[mi][ni][r] = 0.0f;

    #pragma unroll
    for (int ni = 0; ni < 4; ni++)
        #pragma unroll
        for (int ki = 0; ki < 2; ki++) {
            uint32_t bh0 = B2h[ni][ki][0], bh1 = B2h[ni][ki][1];
            uint32_t bl0 = B2l[ni][ki][0], bl1 = B2l[ni][ki][1];
            uint32_t a2h[2][4], a2l[2][4];
            #pragma unroll
            for (int mi = 0; mi < 2; mi++) {
                a2h[mi][0] = Hf[2 * mi][ki][0];  a2h[mi][1] = Hf[2 * mi + 1][ki][0];
                a2h[mi][2] = Hf[2 * mi][ki][1];  a2h[mi][3] = Hf[2 * mi + 1][ki][1];
                a2l[mi][0] = Hfl[2 * mi][ki][0]; a2l[mi][1] = Hfl[2 * mi + 1][ki][0];
                a2l[mi][2] = Hfl[2 * mi][ki][1]; a2l[mi][3] = Hfl[2 * mi + 1][ki][1];
            }
            #pragma unroll
            for (int mi = 0; mi < 2; mi++) mma16816(acc2[mi][ni], a2h[mi], bh0, bh1);
            #pragma unroll
            for (int mi = 0; mi < 2; mi++) mma16816(acc2[mi][ni], a2h[mi], bl0, bl1);
            #pragma unroll
            for (int mi = 0; mi < 2; mi++) mma16816(acc2[mi][ni], a2l[mi], bh0, bh1);
        }

    // ---- store: undo the column permutation by merging even/odd acc pairs
    //      (ni, ni+2) -> 4 consecutive cols: 8 fully-coalesced STG.128 ----
    float* __restrict__ dst = out + ((size_t)blockIdx.x * 4 + w) * 1024;
    #pragma unroll
    for (int mi = 0; mi < 2; mi++) {
        int r0 = 16 * mi + g;
        #pragma unroll
        for (int half = 0; half < 2; half++) {      // ni pair (half, half+2)
            float* e = acc2[mi][half];
            float* o = acc2[mi][half + 2];
            int cbase = 16 * half + 4 * t;
            *reinterpret_cast<float4*>(&dst[r0 * 32 + cbase]) =
                make_float4(e[0], o[0], e[1], o[1]);
            *reinterpret_cast<float4*>(&dst[(r0 + 8) * 32 + cbase]) =
                make_float4(e[2], o[2], e[3], o[3]);
        }
    }
}

extern "C" void kernel_launch(void* const* d_in, const int* in_sizes, int n_in,
                              void* d_out, int out_size)
{
    const float* x = (const float*)d_in[0];   // [B, C, 32, 32] fp32
    const float* H = (const float*)d_in[1];   // [32, 32] fp32
    float* out = (float*)d_out;

    int nMat = in_sizes[0] / 1024;            // 65536 (divisible by 4)
    int blocks = nMat / 4;

    dct2d_mma_kernel<<<blocks, NTHREADS>>>(x, H, out, nMat);
}

// round 16
// speedup vs baseline: 1.4437x; 1.1724x over previous
#include <cuda_runtime.h>
#include <cuda_bf16.h>
#include <cstdint>

// out[b,c] = H @ x[b,c] @ H^T for 65536 independent 32x32 fp32 matrices.
// mma.sync bf16 path, hi/lo split (3 cross terms), fp32 accumulation.
// R15: the DCT even/odd butterfly now applied to BOTH stages:
//   stage 1: U[:,even]=E@He^T, U[:,odd]=O@Ho^T            (24 MMAs)
//   stage 2: out[2l']=He@E2, out[2l'+1]=Ho@O2 where
//            E2/O2[i] = U[i] +/- U[31-i], i<16            (24 MMAs)
// E2/O2 are formed in fp32 on the stage-1 accumulators via one
// shfl.xor(28) exchange (row 31-i lives at lane g^7, same t).
// The full-H table and its fragments are gone (both stages share the
// He/Ho half-tables) -> fewer regs, launch_bounds(128,6) fits.
// Row/column permutations are undone for free in the store epilogue
// (8 fully-coalesced STG.128).

#define NTHREADS 128
#define EPITCH 24                // He/Ho table pitch in bf16 (conflict-free)

__device__ __forceinline__ uint32_t lds32(const unsigned short* p) {
    return *reinterpret_cast<const uint32_t*>(p);
}

__device__ __forceinline__ uint32_t pack_bf16x2(float hi, float lo) {
    uint32_t r;
    asm("cvt.rn.bf16x2.f32 %0, %1, %2;" : "=r"(r) : "f"(hi), "f"(lo));
    return r;
}
__device__ __forceinline__ float bf16lo_f(uint32_t p) {
    return __uint_as_float(p << 16);
}
__device__ __forceinline__ float bf16hi_f(uint32_t p) {
    return __uint_as_float(p & 0xFFFF0000u);
}
// split two f32 (v0=k, v1=k+1) into packed bf16x2 hi + residual lo
__device__ __forceinline__ void split2(float v0, float v1,
                                       uint32_t& h, uint32_t& l) {
    h = pack_bf16x2(v1, v0);
    l = pack_bf16x2(v1 - bf16hi_f(h), v0 - bf16lo_f(h));
}

__device__ __forceinline__ uint32_t movm_t(uint32_t a) {
    uint32_t d;
    asm volatile("movmatrix.sync.aligned.m8n8.trans.b16 %0, %1;"
                 : "=r"(d) : "r"(a));
    return d;
}

__device__ __forceinline__ void mma16816(float* d, const uint32_t* a,
                                         uint32_t b0, uint32_t b1) {
    asm("mma.sync.aligned.m16n8k16.row.col.f32.bf16.bf16.f32 "
        "{%0,%1,%2,%3}, {%4,%5,%6,%7}, {%8,%9}, {%0,%1,%2,%3};"
        : "+f"(d[0]), "+f"(d[1]), "+f"(d[2]), "+f"(d[3])
        : "r"(a[0]), "r"(a[1]), "r"(a[2]), "r"(a[3]), "r"(b0), "r"(b1));
}

__global__ __launch_bounds__(NTHREADS, 6)
void dct2d_mma_kernel(const float* __restrict__ x,
                      const float* __restrict__ H,
                      float* __restrict__ out,
                      int nMat)
{
    __shared__ __align__(16) unsigned short Heh[16 * EPITCH];
    __shared__ __align__(16) unsigned short Hel[16 * EPITCH];
    __shared__ __align__(16) unsigned short Hoh[16 * EPITCH];
    __shared__ __align__(16) unsigned short Hol[16 * EPITCH];

    const int tid  = threadIdx.x;
    const int w    = tid >> 5;
    const int lane = tid & 31;
    const int g    = lane >> 2;   // mma groupID 0..7
    const int t    = lane & 3;    // thread-in-group 0..3

    // ---- issue all X loads FIRST (rows k and partner rows for butterfly) ----
    const float* __restrict__ Xw = x + ((size_t)blockIdx.x * 4 + w) * 1024;
    float2 v0[2][2], v1[2][2], p0[2][2], p1[2][2];
    #pragma unroll
    for (int mi = 0; mi < 2; mi++)
        #pragma unroll
        for (int rh = 0; rh < 2; rh++) {
            const float* rp = Xw + (16 * mi + 8 * rh + g) * 32;
            v0[mi][rh] = *reinterpret_cast<const float2*>(rp + 2 * t);
            v1[mi][rh] = *reinterpret_cast<const float2*>(rp + 8 + 2 * t);
            p0[mi][rh] = *reinterpret_cast<const float2*>(rp + 30 - 2 * t);
            p1[mi][rh] = *reinterpret_cast<const float2*>(rp + 22 - 2 * t);
        }

    // ---- stage the even/odd half-K H tables (only k<16 needed anywhere) ----
    #pragma unroll
    for (int e = tid; e < 512; e += NTHREADS) {
        int r = e >> 4;          // H row 0..31
        int c = e & 15;          // H col 0..15
        float v = H[r * 32 + c];
        __nv_bfloat16 hb = __float2bfloat16_rn(v);
        unsigned short hh = __bfloat16_as_ushort(hb);
        unsigned short hl =
            __bfloat16_as_ushort(__float2bfloat16_rn(v - __bfloat162float(hb)));
        int hr = r >> 1;
        if (r & 1) { Hoh[hr * EPITCH + c] = hh; Hol[hr * EPITCH + c] = hl; }
        else       { Heh[hr * EPITCH + c] = hh; Hel[hr * EPITCH + c] = hl; }
    }
    __syncthreads();

    // ---- stage-1 B frags from He/Ho ----
    uint32_t Beh[2][2], Bel[2][2], Boh[2][2], Bol[2][2];
    #pragma unroll
    for (int ni = 0; ni < 2; ni++) {
        int off = (8 * ni + g) * EPITCH + 2 * t;
        Beh[ni][0] = lds32(Heh + off);  Beh[ni][1] = lds32(Heh + off + 8);
        Bel[ni][0] = lds32(Hel + off);  Bel[ni][1] = lds32(Hel + off + 8);
        Boh[ni][0] = lds32(Hoh + off);  Boh[ni][1] = lds32(Hoh + off + 8);
        Bol[ni][0] = lds32(Hol + off);  Bol[ni][1] = lds32(Hol + off + 8);
    }

    // ---- butterfly E/O in registers + split to stage-1 A frags ----
    uint32_t Aeh[2][4], Ael[2][4], Aoh[2][4], Aol[2][4];
    #pragma unroll
    for (int mi = 0; mi < 2; mi++)
        #pragma unroll
        for (int rh = 0; rh < 2; rh++) {
            float2 a = v0[mi][rh], b = p0[mi][rh];
            float2 c = v1[mi][rh], d = p1[mi][rh];
            float e0 = a.x + b.y, e1 = a.y + b.x;
            float o0 = a.x - b.y, o1 = a.y - b.x;
            float e2 = c.x + d.y, e3 = c.y + d.x;
            float o2 = c.x - d.y, o3 = c.y - d.x;
            split2(e0, e1, Aeh[mi][rh],     Ael[mi][rh]);
            split2(e2, e3, Aeh[mi][2 + rh], Ael[mi][2 + rh]);
            split2(o0, o1, Aoh[mi][rh],     Aol[mi][rh]);
            split2(o2, o3, Aoh[mi][2 + rh], Aol[mi][2 + rh]);
        }

    // ============ stage 1: Utilde = [E@He^T | O@Ho^T] (24 MMAs) ============
    float acc[2][4][4];
    #pragma unroll
    for (int mi = 0; mi < 2; mi++)
        #pragma unroll
        for (int ni = 0; ni < 4; ni++)
            #pragma unroll
            for (int r = 0; r < 4; r++) acc[mi][ni][r] = 0.0f;

    #pragma unroll
    for (int ni = 0; ni < 2; ni++) {
        #pragma unroll
        for (int mi = 0; mi < 2; mi++) mma16816(acc[mi][ni],     Aeh[mi], Beh[ni][0], Beh[ni][1]);
        #pragma unroll
        for (int mi = 0; mi < 2; mi++) mma16816(acc[mi][2 + ni], Aoh[mi], Boh[ni][0], Boh[ni][1]);
        #pragma unroll
        for (int mi = 0; mi < 2; mi++) mma16816(acc[mi][ni],     Aeh[mi], Bel[ni][0], Bel[ni][1]);
        #pragma unroll
        for (int mi = 0; mi < 2; mi++) mma16816(acc[mi][2 + ni], Aoh[mi], Bol[ni][0], Bol[ni][1]);
        #pragma unroll
        for (int mi = 0; mi < 2; mi++) mma16816(acc[mi][ni],     Ael[mi], Beh[ni][0], Beh[ni][1]);
        #pragma unroll
        for (int mi = 0; mi < 2; mi++) mma16816(acc[mi][2 + ni], Aol[mi], Boh[ni][0], Boh[ni][1]);
    }

    // ---- stage-2 A frags (He/Ho reused; start LDS latency early) ----
    uint32_t A2eh[4], A2el[4], A2oh[4], A2ol[4];
    {
        int off = g * EPITCH + 2 * t;
        A2eh[0] = lds32(Heh + off);
        A2eh[1] = lds32(Heh + off + 8 * EPITCH);
        A2eh[2] = lds32(Heh + off + 8);
        A2eh[3] = lds32(Heh + off + 8 * EPITCH + 8);
        A2el[0] = lds32(Hel + off);
        A2el[1] = lds32(Hel + off + 8 * EPITCH);
        A2el[2] = lds32(Hel + off + 8);
        A2el[3] = lds32(Hel + off + 8 * EPITCH + 8);
        A2oh[0] = lds32(Hoh + off);
        A2oh[1] = lds32(Hoh + off + 8 * EPITCH);
        A2oh[2] = lds32(Hoh + off + 8);
        A2oh[3] = lds32(Hoh + off + 8 * EPITCH + 8);
        A2ol[0] = lds32(Hol + off);
        A2ol[1] = lds32(Hol + off + 8 * EPITCH);
        A2ol[2] = lds32(Hol + off + 8);
        A2ol[3] = lds32(Hol + off + 8 * EPITCH + 8);
    }

    // ---- stage-2 butterfly on accumulators: E2/O2[i] = U[i] +/- U[31-i] ----
    // Row 31-i lives at lane^28 (g<->7-g): mi=1 acc, row-halves swapped.
    float e2[4][4], o2[4][4];
    #pragma unroll
    for (int ni = 0; ni < 4; ni++) {
        float s0 = __shfl_xor_sync(0xffffffffu, acc[1][ni][0], 28);
        float s1 = __shfl_xor_sync(0xffffffffu, acc[1][ni][1], 28);
        float s2 = __shfl_xor_sync(0xffffffffu, acc[1][ni][2], 28);
        float s3 = __shfl_xor_sync(0xffffffffu, acc[1][ni][3], 28);
        e2[ni][0] = acc[0][ni][0] + s2;  o2[ni][0] = acc[0][ni][0] - s2;
        e2[ni][1] = acc[0][ni][1] + s3;  o2[ni][1] = acc[0][ni][1] - s3;
        e2[ni][2] = acc[0][ni][2] + s0;  o2[ni][2] = acc[0][ni][2] - s0;
        e2[ni][3] = acc[0][ni][3] + s1;  o2[ni][3] = acc[0][ni][3] - s1;
    }

    // ---- handoff: split + in-register transpose (one K=16 chunk each) ----
    uint32_t Be2h[4][2], Be2l[4][2], Bo2h[4][2], Bo2l[4][2];
    #pragma unroll
    for (int ni = 0; ni < 4; ni++) {
        uint32_t h01, l01, h23, l23;
        split2(e2[ni][0], e2[ni][1], h01, l01);
        split2(e2[ni][2], e2[ni][3], h23, l23);
        Be2h[ni][0] = movm_t(h01);  Be2h[ni][1] = movm_t(h23);
        Be2l[ni][0] = movm_t(l01);  Be2l[ni][1] = movm_t(l23);
        split2(o2[ni][0], o2[ni][1], h01, l01);
        split2(o2[ni][2], o2[ni][3], h23, l23);
        Bo2h[ni][0] = movm_t(h01);  Bo2h[ni][1] = movm_t(h23);
        Bo2l[ni][0] = movm_t(l01);  Bo2l[ni][1] = movm_t(l23);
    }

    // ========= stage 2: out_even = He@E2, out_odd = Ho@O2 (24 MMAs) ========
    float ae[4][4], ao[4][4];
    #pragma unroll
    for (int ni = 0; ni < 4; ni++)
        #pragma unroll
        for (int r = 0; r < 4; r++) { ae[ni][r] = 0.0f; ao[ni][r] = 0.0f; }

    #pragma unroll
    for (int ni = 0; ni < 4; ni++) {
        mma16816(ae[ni], A2eh, Be2h[ni][0], Be2h[ni][1]);
        mma16816(ao[ni], A2oh, Bo2h[ni][0], Bo2h[ni][1]);
        mma16816(ae[ni], A2eh, Be2l[ni][0], Be2l[ni][1]);
        mma16816(ao[ni], A2oh, Bo2l[ni][0], Bo2l[ni][1]);
        mma16816(ae[ni], A2el, Be2h[ni][0], Be2h[ni][1]);
        mma16816(ao[ni], A2ol, Bo2h[ni][0], Bo2h[ni][1]);
    }

    // ---- store: undo both permutations; 8 fully-coalesced STG.128 ----
    // rows: ae -> 2g, 2g+16; ao -> 2g+1, 2g+17.
    // cols: merge ni-pair (half, half+2) -> 4 consecutive cols.
    float* __restrict__ dst = out + ((size_t)blockIdx.x * 4 + w) * 1024;
    #pragma unroll
    for (int half = 0; half < 2; half++) {
        int cbase = 16 * half + 4 * t;
        float* Ee = ae[half];  float* Eo = ae[half + 2];
        float* Oe = ao[half];  float* Oo = ao[half + 2];
        *reinterpret_cast<float4*>(&dst[(2 * g) * 32 + cbase]) =
            make_float4(Ee[0], Eo[0], Ee[1], Eo[1]);
        *reinterpret_cast<float4*>(&dst[(2 * g + 16) * 32 + cbase]) =
            make_float4(Ee[2], Eo[2], Ee[3], Eo[3]);
        *reinterpret_cast<float4*>(&dst[(2 * g + 1) * 32 + cbase]) =
            make_float4(Oe[0], Oo[0], Oe[1], Oo[1]);
        *reinterpret_cast<float4*>(&dst[(2 * g + 17) * 32 + cbase]) =
            make_float4(Oe[2], Oo[2], Oe[3], Oo[3]);
    }
}

extern "C" void kernel_launch(void* const* d_in, const int* in_sizes, int n_in,
                              void* d_out, int out_size)
{
    const float* x = (const float*)d_in[0];   // [B, C, 32, 32] fp32
    const float* H = (const float*)d_in[1];   // [32, 32] fp32
    float* out = (float*)d_out;

    int nMat = in_sizes[0] / 1024;            // 65536 (divisible by 4)
    int blocks = nMat / 4;

    dct2d_mma_kernel<<<blocks, NTHREADS>>>(x, H, out, nMat);
}